// round 4
// baseline (speedup 1.0000x reference)
#include <cuda_runtime.h>
#include <cuda_bf16.h>

// qpNet: z = max(-(x @ W^T + b), -1/EPS), EPS=1e-3  =>  z = max(-h, -1000)
// x: [B,5] f32, W: [5,5] f32, b: [5] f32, out: [B,5] f32. B = 4194304.
//
// R4: R3 smem-staged coalescing + occupancy 6 blocks/SM (launch_bounds) +
// middle barrier removed (thread t reads AND writes only its own smem slots
// {5t..5t+4}, so the z write-back has no cross-thread hazard).

#define NEG_CLAMP (-1000.0f)   // -1/EPS

__global__ __launch_bounds__(256, 6) void qp_kernel(
    const float* __restrict__ x,
    const float* __restrict__ W,
    const float* __restrict__ b,
    float* __restrict__ out)
{
    __shared__ float4 tile[1280];   // 20 KB = 256 threads * 5 float4

    const int tid = threadIdx.x;
    const long long gbase4 = (long long)blockIdx.x * 1280;  // float4 index

    // ---- coalesced stage-in: 5 float4 per thread, lane-contiguous ----
    const float4* __restrict__ x4 = reinterpret_cast<const float4*>(x);
#pragma unroll
    for (int i = 0; i < 5; i++)
        tile[tid + 256 * i] = x4[gbase4 + tid + 256 * i];

    // ---- W [5,5] + b [5]: 9 vectorized loads (L1/L2 hits after 1st wave) ----
    float w[5][5], bb[5];
    {
        const float4* W4 = reinterpret_cast<const float4*>(W);
        float4 a0 = __ldg(W4 + 0);
        float4 a1 = __ldg(W4 + 1);
        float4 a2 = __ldg(W4 + 2);
        float4 a3 = __ldg(W4 + 3);
        float4 a4 = __ldg(W4 + 4);
        float4 a5 = __ldg(W4 + 5);
        float  a6 = __ldg(W + 24);
        w[0][0]=a0.x; w[0][1]=a0.y; w[0][2]=a0.z; w[0][3]=a0.w; w[0][4]=a1.x;
        w[1][0]=a1.y; w[1][1]=a1.z; w[1][2]=a1.w; w[1][3]=a2.x; w[1][4]=a2.y;
        w[2][0]=a2.z; w[2][1]=a2.w; w[2][2]=a3.x; w[2][3]=a3.y; w[2][4]=a3.z;
        w[3][0]=a3.w; w[3][1]=a4.x; w[3][2]=a4.y; w[3][3]=a4.z; w[3][4]=a4.w;
        w[4][0]=a5.x; w[4][1]=a5.y; w[4][2]=a5.z; w[4][3]=a5.w; w[4][4]=a6;
        const float4* b4 = reinterpret_cast<const float4*>(b);
        float4 bv = __ldg(b4);
        bb[0]=bv.x; bb[1]=bv.y; bb[2]=bv.z; bb[3]=bv.w; bb[4]=__ldg(b + 4);
    }

    __syncthreads();   // stage-in visible to all

    // ---- read own 4 rows (20 floats) via 5x LDS.128, conflict-free ----
    float4 v[5];
#pragma unroll
    for (int i = 0; i < 5; i++)
        v[i] = tile[5 * tid + i];

    float xr[4][5];
    xr[0][0]=v[0].x; xr[0][1]=v[0].y; xr[0][2]=v[0].z; xr[0][3]=v[0].w; xr[0][4]=v[1].x;
    xr[1][0]=v[1].y; xr[1][1]=v[1].z; xr[1][2]=v[1].w; xr[1][3]=v[2].x; xr[1][4]=v[2].y;
    xr[2][0]=v[2].z; xr[2][1]=v[2].w; xr[2][2]=v[3].x; xr[2][3]=v[3].y; xr[2][4]=v[3].z;
    xr[3][0]=v[3].w; xr[3][1]=v[4].x; xr[3][2]=v[4].y; xr[3][3]=v[4].z; xr[3][4]=v[4].w;

    float zr[4][5];
#pragma unroll
    for (int r = 0; r < 4; r++) {
#pragma unroll
        for (int j = 0; j < 5; j++) {
            float h = bb[j];
#pragma unroll
            for (int k = 0; k < 5; k++)
                h = fmaf(xr[r][k], w[j][k], h);
            zr[r][j] = fmaxf(-h, NEG_CLAMP);
        }
    }

    // NO barrier needed here: thread t read only slots {5t..5t+4} and now
    // writes z back only to those same slots — within-thread hazard only.
    tile[5 * tid + 0] = make_float4(zr[0][0], zr[0][1], zr[0][2], zr[0][3]);
    tile[5 * tid + 1] = make_float4(zr[0][4], zr[1][0], zr[1][1], zr[1][2]);
    tile[5 * tid + 2] = make_float4(zr[1][3], zr[1][4], zr[2][0], zr[2][1]);
    tile[5 * tid + 3] = make_float4(zr[2][2], zr[2][3], zr[2][4], zr[3][0]);
    tile[5 * tid + 4] = make_float4(zr[3][1], zr[3][2], zr[3][3], zr[3][4]);

    __syncthreads();   // z visible before coalesced stage-out

    // ---- coalesced stage-out ----
    float4* __restrict__ o4 = reinterpret_cast<float4*>(out);
#pragma unroll
    for (int i = 0; i < 5; i++)
        o4[gbase4 + tid + 256 * i] = tile[tid + 256 * i];
}

extern "C" void kernel_launch(void* const* d_in, const int* in_sizes, int n_in,
                              void* d_out, int out_size)
{
    const float* x = (const float*)d_in[0];   // [B,5]
    const float* W = (const float*)d_in[1];   // [5,5]
    const float* b = (const float*)d_in[2];   // [5]
    float* out = (float*)d_out;               // [B,5]

    const long long B = in_sizes[0] / 5;      // 4194304
    const int threads = 256;
    // 1024 rows per block -> 4096 blocks, exact cover (B % 1024 == 0)
    const int blocks = (int)(B / 1024);

    qp_kernel<<<blocks, threads>>>(x, W, b, out);
}

// round 5
// speedup vs baseline: 1.4303x; 1.4303x over previous
#include <cuda_runtime.h>
#include <cuda_bf16.h>
#include <cstdint>

// qpNet: z = max(-(x @ W^T + b), -1/EPS), EPS=1e-3  =>  z = max(-h, -1000)
// x: [B,5] f32, W: [5,5] f32, b: [5] f32, out: [B,5] f32. B = 4194304.
//
// R5: 1D bulk-TMA staging (cp.async.bulk) replaces per-lane LDG/STG staging.
// Per-warp LSU work per 20KB tile: only 5 LDS.128 + 5 STS.128 (conflict-free,
// 80B stride). Global<->smem movement rides the bulk-copy engine.

#define NEG_CLAMP   (-1000.0f)   // -1/EPS
#define TILE_BYTES  20480u       // 1024 rows * 5 floats * 4 B

__global__ __launch_bounds__(256) void qp_kernel(
    const float* __restrict__ x,
    const float* __restrict__ W,
    const float* __restrict__ b,
    float* __restrict__ out)
{
    __shared__ alignas(128) float4 tile[1280];          // 20 KB
    __shared__ alignas(8)   unsigned long long mbar;

    const int tid = threadIdx.x;
    const long long base_f = (long long)blockIdx.x * 5120;  // float offset

    const unsigned mb = (unsigned)__cvta_generic_to_shared(&mbar);
    const unsigned st = (unsigned)__cvta_generic_to_shared(tile);
    const unsigned long long src = (unsigned long long)(uintptr_t)(x + base_f);
    const unsigned long long dst = (unsigned long long)(uintptr_t)(out + base_f);

    // ---- init mbarrier, then issue bulk TMA load of the tile ----
    if (tid == 0)
        asm volatile("mbarrier.init.shared.b64 [%0], %1;" :: "r"(mb), "r"(1u));
    __syncthreads();
    if (tid == 0) {
        asm volatile("mbarrier.arrive.expect_tx.shared.b64 _, [%0], %1;"
                     :: "r"(mb), "r"(TILE_BYTES) : "memory");
        asm volatile("cp.async.bulk.shared::cta.global.mbarrier::complete_tx::bytes "
                     "[%0], [%1], %2, [%3];"
                     :: "r"(st), "l"(src), "r"(TILE_BYTES), "r"(mb) : "memory");
    }

    // ---- W [5,5] + b [5] while TMA is in flight (L1/L2 hits after wave 1) ----
    float w[5][5], bb[5];
    {
        const float4* W4 = reinterpret_cast<const float4*>(W);
        float4 a0 = __ldg(W4 + 0);
        float4 a1 = __ldg(W4 + 1);
        float4 a2 = __ldg(W4 + 2);
        float4 a3 = __ldg(W4 + 3);
        float4 a4 = __ldg(W4 + 4);
        float4 a5 = __ldg(W4 + 5);
        float  a6 = __ldg(W + 24);
        w[0][0]=a0.x; w[0][1]=a0.y; w[0][2]=a0.z; w[0][3]=a0.w; w[0][4]=a1.x;
        w[1][0]=a1.y; w[1][1]=a1.z; w[1][2]=a1.w; w[1][3]=a2.x; w[1][4]=a2.y;
        w[2][0]=a2.z; w[2][1]=a2.w; w[2][2]=a3.x; w[2][3]=a3.y; w[2][4]=a3.z;
        w[3][0]=a3.w; w[3][1]=a4.x; w[3][2]=a4.y; w[3][3]=a4.z; w[3][4]=a4.w;
        w[4][0]=a5.x; w[4][1]=a5.y; w[4][2]=a5.z; w[4][3]=a5.w; w[4][4]=a6;
        const float4* b4 = reinterpret_cast<const float4*>(b);
        float4 bv = __ldg(b4);
        bb[0]=bv.x; bb[1]=bv.y; bb[2]=bv.z; bb[3]=bv.w; bb[4]=__ldg(b + 4);
    }

    // ---- wait for tile (acquire: generic ld.shared follows) ----
    asm volatile(
        "{\n\t"
        ".reg .pred P;\n\t"
        "WAIT_%=:\n\t"
        "mbarrier.try_wait.parity.acquire.cta.shared::cta.b64 P, [%0], 0, 0x989680;\n\t"
        "@P bra DONE_%=;\n\t"
        "bra WAIT_%=;\n\t"
        "DONE_%=:\n\t"
        "}"
        :: "r"(mb) : "memory");

    // ---- read own 4 rows (20 floats) via 5x LDS.128, conflict-free ----
    float4 v[5];
#pragma unroll
    for (int i = 0; i < 5; i++)
        v[i] = tile[5 * tid + i];

    float xr[4][5];
    xr[0][0]=v[0].x; xr[0][1]=v[0].y; xr[0][2]=v[0].z; xr[0][3]=v[0].w; xr[0][4]=v[1].x;
    xr[1][0]=v[1].y; xr[1][1]=v[1].z; xr[1][2]=v[1].w; xr[1][3]=v[2].x; xr[1][4]=v[2].y;
    xr[2][0]=v[2].z; xr[2][1]=v[2].w; xr[2][2]=v[3].x; xr[2][3]=v[3].y; xr[2][4]=v[3].z;
    xr[3][0]=v[3].w; xr[3][1]=v[4].x; xr[3][2]=v[4].y; xr[3][3]=v[4].z; xr[3][4]=v[4].w;

    float zr[4][5];
#pragma unroll
    for (int r = 0; r < 4; r++) {
#pragma unroll
        for (int j = 0; j < 5; j++) {
            float h = bb[j];
#pragma unroll
            for (int k = 0; k < 5; k++)
                h = fmaf(xr[r][k], w[j][k], h);
            zr[r][j] = fmaxf(-h, NEG_CLAMP);
        }
    }

    // Write-back to own slots only (within-thread hazard; no barrier needed).
    tile[5 * tid + 0] = make_float4(zr[0][0], zr[0][1], zr[0][2], zr[0][3]);
    tile[5 * tid + 1] = make_float4(zr[0][4], zr[1][0], zr[1][1], zr[1][2]);
    tile[5 * tid + 2] = make_float4(zr[1][3], zr[1][4], zr[2][0], zr[2][1]);
    tile[5 * tid + 3] = make_float4(zr[2][2], zr[2][3], zr[2][4], zr[3][0]);
    tile[5 * tid + 4] = make_float4(zr[3][1], zr[3][2], zr[3][3], zr[3][4]);

    __syncthreads();   // all z in smem before bulk store reads it

    // ---- bulk TMA store: smem -> global ----
    if (tid == 0) {
        asm volatile("fence.proxy.async.shared::cta;" ::: "memory");
        asm volatile("cp.async.bulk.global.shared::cta.bulk_group [%0], [%1], %2;"
                     :: "l"(dst), "r"(st), "r"(TILE_BYTES) : "memory");
        asm volatile("cp.async.bulk.commit_group;" ::: "memory");
        // Wait until the bulk engine has READ the smem (CTA may then exit).
        asm volatile("cp.async.bulk.wait_group.read 0;" ::: "memory");
    }
}

extern "C" void kernel_launch(void* const* d_in, const int* in_sizes, int n_in,
                              void* d_out, int out_size)
{
    const float* x = (const float*)d_in[0];   // [B,5]
    const float* W = (const float*)d_in[1];   // [5,5]
    const float* b = (const float*)d_in[2];   // [5]
    float* out = (float*)d_out;               // [B,5]

    const long long B = in_sizes[0] / 5;      // 4194304
    const int threads = 256;
    // 1024 rows per block -> 4096 blocks, exact cover (B % 1024 == 0)
    const int blocks = (int)(B / 1024);

    qp_kernel<<<blocks, threads>>>(x, W, b, out);
}